// round 1
// baseline (speedup 1.0000x reference)
#include <cuda_runtime.h>
#include <math.h>

// ---------------------------------------------------------------------------
// DoubleAttention: B=32, C=512, H=W=32 (N=1024), Cout=dn=512
//   A  = wA@x + bA            [B,512,1024]
//   Bm = softmax(wB@x + bB)   [B,512,1024]  (softmax over N)
//   Vm = softmax(wV@x + bV)   [B,512,1024]
//   G  = A @ Bm^T             [B,512,512]
//   G2 = wR @ G               [B,512,512]   (fused: wR@(G@Vm) == (wR@G)@Vm)
//   out= G2 @ Vm + bR         [B,512,1024]
// ---------------------------------------------------------------------------

#define BSZ   32
#define CDIM  512
#define NDIM  1024

// Scratch (device globals — no runtime allocation allowed)
__device__ float g_A [(size_t)BSZ * CDIM * NDIM];   // 64 MB
__device__ float g_Bm[(size_t)BSZ * CDIM * NDIM];   // 64 MB
__device__ float g_Vm[(size_t)BSZ * CDIM * NDIM];   // 64 MB
__device__ float g_G [(size_t)BSZ * CDIM * CDIM];   // 32 MB
__device__ float g_G2[(size_t)BSZ * CDIM * CDIM];   // 32 MB

#define BM 128
#define BN 128
#define BK 8

// Generic batched SGEMM: C[b] = A[b] (MxK) * B[b] (KxN or NxK if TB) (+ bias[row])
// All row-major. M,N multiples of 128; K multiple of 8. 256 threads, 8x8/thread.
template<bool TB, bool BIAS>
__global__ __launch_bounds__(256, 2)
void sgemm_kernel(const float* __restrict__ Ag, long long sA,
                  const float* __restrict__ Bg, long long sB,
                  const float* __restrict__ bias,
                  float*       __restrict__ Cg, long long sC,
                  int M, int N, int K)
{
    const int b = blockIdx.z;
    const float* A = Ag + (long long)b * sA;
    const float* B = Bg + (long long)b * sB;
    float*       C = Cg + (long long)b * sC;

    __shared__ float As[BK][BM];
    __shared__ float Bs[BK][BN + 4];

    const int tid = threadIdx.x;
    const int tx = tid & 15;          // 0..15 -> column group
    const int ty = tid >> 4;          // 0..15 -> row group
    const int row0 = blockIdx.y * BM + ty * 8;
    const int col0 = blockIdx.x * BN + tx * 8;

    float acc[8][8];
#pragma unroll
    for (int i = 0; i < 8; i++)
#pragma unroll
        for (int j = 0; j < 8; j++) acc[i][j] = 0.f;

    // A-tile load mapping: 128 rows x 8 k (2 float4 per row)
    const int a_r = tid >> 1;
    const int a_c = (tid & 1) * 4;
    // B-tile (NN): 8 rows x 128 cols
    const int b_r = tid >> 5;
    const int b_c = (tid & 31) * 4;
    // B-tile (NT): 128 n-rows x 8 k
    const int bt_n = tid >> 1;
    const int bt_k = (tid & 1) * 4;

    for (int k0 = 0; k0 < K; k0 += BK) {
        // Load A tile (transpose into As[k][m])
        float4 av = *(const float4*)(A + (long long)(blockIdx.y * BM + a_r) * K + k0 + a_c);
        As[a_c + 0][a_r] = av.x;
        As[a_c + 1][a_r] = av.y;
        As[a_c + 2][a_r] = av.z;
        As[a_c + 3][a_r] = av.w;

        if (!TB) {
            float4 bv = *(const float4*)(B + (long long)(k0 + b_r) * N + blockIdx.x * BN + b_c);
            *(float4*)&Bs[b_r][b_c] = bv;
        } else {
            float4 bv = *(const float4*)(B + (long long)(blockIdx.x * BN + bt_n) * K + k0 + bt_k);
            Bs[bt_k + 0][bt_n] = bv.x;
            Bs[bt_k + 1][bt_n] = bv.y;
            Bs[bt_k + 2][bt_n] = bv.z;
            Bs[bt_k + 3][bt_n] = bv.w;
        }
        __syncthreads();

#pragma unroll
        for (int kk = 0; kk < BK; kk++) {
            float ar[8], br[8];
            *(float4*)&ar[0] = *(const float4*)&As[kk][ty * 8 + 0];
            *(float4*)&ar[4] = *(const float4*)&As[kk][ty * 8 + 4];
            *(float4*)&br[0] = *(const float4*)&Bs[kk][tx * 8 + 0];
            *(float4*)&br[4] = *(const float4*)&Bs[kk][tx * 8 + 4];
#pragma unroll
            for (int i = 0; i < 8; i++)
#pragma unroll
                for (int j = 0; j < 8; j++)
                    acc[i][j] = fmaf(ar[i], br[j], acc[i][j]);
        }
        __syncthreads();
    }

#pragma unroll
    for (int i = 0; i < 8; i++) {
        float bv = BIAS ? bias[row0 + i] : 0.f;
        float4 v0, v1;
        v0.x = acc[i][0] + bv; v0.y = acc[i][1] + bv;
        v0.z = acc[i][2] + bv; v0.w = acc[i][3] + bv;
        v1.x = acc[i][4] + bv; v1.y = acc[i][5] + bv;
        v1.z = acc[i][6] + bv; v1.w = acc[i][7] + bv;
        *(float4*)(C + (long long)(row0 + i) * N + col0 + 0) = v0;
        *(float4*)(C + (long long)(row0 + i) * N + col0 + 4) = v1;
    }
}

// In-place row softmax over rows of length 1024; one block (256 thr) per row.
__global__ __launch_bounds__(256)
void softmax_rows_kernel(float* __restrict__ data)
{
    float* row = data + (long long)blockIdx.x * NDIM;
    const int tid = threadIdx.x;

    float4 v = *(const float4*)(row + tid * 4);

    // max reduce
    float m = fmaxf(fmaxf(v.x, v.y), fmaxf(v.z, v.w));
#pragma unroll
    for (int off = 16; off > 0; off >>= 1)
        m = fmaxf(m, __shfl_xor_sync(0xffffffffu, m, off));
    __shared__ float smax[8];
    __shared__ float ssum[8];
    const int wid = tid >> 5, lid = tid & 31;
    if (lid == 0) smax[wid] = m;
    __syncthreads();
    if (wid == 0) {
        float t = smax[lid & 7];
#pragma unroll
        for (int off = 4; off > 0; off >>= 1)
            t = fmaxf(t, __shfl_xor_sync(0xffffffffu, t, off));
        if (lid == 0) smax[0] = t;
    }
    __syncthreads();
    m = smax[0];

    // exp + sum
    v.x = __expf(v.x - m) ; // fast exp; |err| ~1e-6 relative, fine at 1e-3 bar
    v.y = __expf(v.y - m);
    v.z = __expf(v.z - m);
    v.w = __expf(v.w - m);
    float s = v.x + v.y + v.z + v.w;
#pragma unroll
    for (int off = 16; off > 0; off >>= 1)
        s += __shfl_xor_sync(0xffffffffu, s, off);
    if (lid == 0) ssum[wid] = s;
    __syncthreads();
    if (wid == 0) {
        float t = ssum[lid & 7];
#pragma unroll
        for (int off = 4; off > 0; off >>= 1)
            t += __shfl_xor_sync(0xffffffffu, t, off);
        if (lid == 0) ssum[0] = t;
    }
    __syncthreads();
    const float inv = 1.0f / ssum[0];

    v.x *= inv; v.y *= inv; v.z *= inv; v.w *= inv;
    *(float4*)(row + tid * 4) = v;
}

extern "C" void kernel_launch(void* const* d_in, const int* in_sizes, int n_in,
                              void* d_out, int out_size)
{
    const float* x  = (const float*)d_in[0];
    const float* wA = (const float*)d_in[1];
    const float* bA = (const float*)d_in[2];
    const float* wB = (const float*)d_in[3];
    const float* bB = (const float*)d_in[4];
    const float* wV = (const float*)d_in[5];
    const float* bV = (const float*)d_in[6];
    const float* wR = (const float*)d_in[7];
    const float* bR = (const float*)d_in[8];
    float* out = (float*)d_out;

    float *gA, *gBm, *gVm, *gG, *gG2;
    cudaGetSymbolAddress((void**)&gA,  g_A);
    cudaGetSymbolAddress((void**)&gBm, g_Bm);
    cudaGetSymbolAddress((void**)&gVm, g_Vm);
    cudaGetSymbolAddress((void**)&gG,  g_G);
    cudaGetSymbolAddress((void**)&gG2, g_G2);

    const long long sXN = (long long)CDIM * NDIM;  // 512*1024
    const long long sCC = (long long)CDIM * CDIM;  // 512*512

    dim3 blk(256);

    // K1: A/Bm/Vm projections  (M=512, N=1024, K=512)
    dim3 g1(NDIM / BN, CDIM / BM, BSZ);
    sgemm_kernel<false, true><<<g1, blk>>>(wA, 0, x, sXN, bA, gA,  sXN, CDIM, NDIM, CDIM);
    sgemm_kernel<false, true><<<g1, blk>>>(wB, 0, x, sXN, bB, gBm, sXN, CDIM, NDIM, CDIM);
    sgemm_kernel<false, true><<<g1, blk>>>(wV, 0, x, sXN, bV, gVm, sXN, CDIM, NDIM, CDIM);

    // K2: softmax over spatial dim
    softmax_rows_kernel<<<BSZ * CDIM, blk>>>(gBm);
    softmax_rows_kernel<<<BSZ * CDIM, blk>>>(gVm);

    // K3: G = A @ Bm^T   (M=512, N=512, K=1024, NT)
    dim3 g3(CDIM / BN, CDIM / BM, BSZ);
    sgemm_kernel<true, false><<<g3, blk>>>(gA, sXN, gBm, sXN, nullptr, gG, sCC, CDIM, CDIM, NDIM);

    // K4: G2 = wR @ G    (M=512, N=512, K=512, NN)
    sgemm_kernel<false, false><<<g3, blk>>>(wR, 0, gG, sCC, nullptr, gG2, sCC, CDIM, CDIM, CDIM);

    // K5: out = G2 @ Vm + bR  (M=512, N=1024, K=512, NN)
    sgemm_kernel<false, true><<<g1, blk>>>(gG2, sCC, gVm, sXN, bR, out, sXN, CDIM, NDIM, CDIM);
}

// round 3
// speedup vs baseline: 2.1574x; 2.1574x over previous
#include <cuda_runtime.h>
#include <cstdint>

// ---------------------------------------------------------------------------
// DoubleAttention via mma.sync tf32 (sm_103-safe; no tcgen05 — harness PTX
// target lacks the 'a' suffix, so arch-specific instructions are unavailable).
// B=32, C=Cout=dn=512, N=1024.
//   A  = wA@x + bA         (NN)
//   Bm = softmax(wB@x+bB)  (NN + softmax)
//   Vm = softmax(wV@x+bV)
//   G  = A @ Bm^T          (NT)
//   G2 = wR @ G            (NN)    [wR@(G@Pv) == (wR@G)@Pv fusion]
//   out= G2 @ Vm + bR      (NN)
// No transposes needed: SMEM staging handles both layouts.
// ---------------------------------------------------------------------------

#define BSZ   32
#define CDIM  512
#define NDIM  1024

__device__ float g_A  [(size_t)BSZ * CDIM * NDIM];
__device__ float g_Bm [(size_t)BSZ * CDIM * NDIM];
__device__ float g_Vm [(size_t)BSZ * CDIM * NDIM];
__device__ float g_G  [(size_t)BSZ * CDIM * CDIM];
__device__ float g_G2 [(size_t)BSZ * CDIM * CDIM];

__device__ __forceinline__ uint32_t smem_u32(const void* p) {
    uint32_t a;
    asm("{ .reg .u64 t; cvta.to.shared.u64 t, %1; cvt.u32.u64 %0, t; }"
        : "=r"(a) : "l"(p));
    return a;
}

__device__ __forceinline__ void cp16(uint32_t dst, const void* src) {
    asm volatile("cp.async.cg.shared.global [%0], [%1], 16;"
                 :: "r"(dst), "l"(src));
}

__device__ __forceinline__ uint32_t to_tf32_u(float x) {
    float y;
    asm("cvt.rna.tf32.f32 %0, %1;" : "=f"(y) : "f"(x));
    return __float_as_uint(y);
}

// ---------------------------------------------------------------------------
// Tensor-core GEMM: C[b][m][n] = sum_k A[b][m][k] * B[b][k][n]   (TB=false)
//                              = sum_k A[b][m][k] * B[b][n][k]   (TB=true)
// CTA 128x128, 256 thr (8 warps of 64x32), BK=16, 2-stage cp.async pipeline,
// mma.sync.m16n8k8 tf32.
// ---------------------------------------------------------------------------
// SMEM pitches (floats):
//   A tile [128 m][16 k], pitch 20  -> frag reads conflict-free
//   B NN   [16 k][128 n], pitch 136 -> (k*136+n)%32 = (k*8+n)%32 all distinct
//   B NT   [128 n][16 k], pitch 20  -> same as A
#define PA 20
#define PBNN 136

template<bool TB, bool BIAS>
__global__ void __launch_bounds__(256)
mma_gemm_kernel(const float* __restrict__ Ag, size_t sAs, int lda,
                const float* __restrict__ Bg, size_t sBs, int ldb,
                const float* __restrict__ bias,
                float* __restrict__ Cg, size_t sCs, int ldc, int K)
{
    __shared__ float shA[2][128 * PA];      // 10240 B per stage
    __shared__ float shB[2][128 * PA];      // NT uses 128*20; NN uses 16*136=2176 < 2560

    const int tid  = threadIdx.x;
    const int lane = tid & 31;
    const int wid  = tid >> 5;
    const int wm   = wid & 1;               // 2 warps along m
    const int wn   = wid >> 1;              // 4 warps along n
    const int m0   = wm * 64;
    const int n0   = wn * 32;
    const int row0 = blockIdx.y * 128;
    const int col0 = blockIdx.x * 128;

    const float* A = Ag + (size_t)blockIdx.z * sAs;
    const float* B = Bg + (size_t)blockIdx.z * sBs;
    float*       C = Cg + (size_t)blockIdx.z * sCs;

    const uint32_t saA[2] = { smem_u32(shA[0]), smem_u32(shA[1]) };
    const uint32_t saB[2] = { smem_u32(shB[0]), smem_u32(shB[1]) };

    float acc[4][4][4];
#pragma unroll
    for (int i = 0; i < 4; i++)
#pragma unroll
        for (int j = 0; j < 4; j++)
#pragma unroll
            for (int r = 0; r < 4; r++) acc[i][j][r] = 0.f;

    const int nch = K >> 4;

    // ---- staging (2 x 16B chunks per thread per operand) ----
    auto load_stage = [&](int s, int k0) {
#pragma unroll
        for (int i = 0; i < 2; i++) {
            const int c  = tid + i * 256;         // 0..511
            const int r  = c >> 2;                // 0..127
            const int cc = c & 3;                 // 16B chunk in row
            cp16(saA[s] + (uint32_t)(r * PA + cc * 4) * 4,
                 A + (size_t)(row0 + r) * lda + k0 + cc * 4);
        }
        if (!TB) {
#pragma unroll
            for (int i = 0; i < 2; i++) {
                const int c  = tid + i * 256;     // 0..511
                const int r  = c >> 5;            // 0..15 (k)
                const int cc = c & 31;            // 16B chunk in 512B row
                cp16(saB[s] + (uint32_t)(r * PBNN + cc * 4) * 4,
                     B + (size_t)(k0 + r) * ldb + col0 + cc * 4);
            }
        } else {
#pragma unroll
            for (int i = 0; i < 2; i++) {
                const int c  = tid + i * 256;
                const int r  = c >> 2;            // 0..127 (n)
                const int cc = c & 3;
                cp16(saB[s] + (uint32_t)(r * PA + cc * 4) * 4,
                     B + (size_t)(col0 + r) * ldb + k0 + cc * 4);
            }
        }
        asm volatile("cp.async.commit_group;" ::: "memory");
    };

    load_stage(0, 0);

    const int lr = lane >> 2;   // 0..7
    const int lc = lane & 3;    // 0..3

    for (int ch = 0; ch < nch; ++ch) {
        const int s = ch & 1;
        if (ch + 1 < nch) {
            load_stage(s ^ 1, (ch + 1) << 4);
            asm volatile("cp.async.wait_group 1;" ::: "memory");
        } else {
            asm volatile("cp.async.wait_group 0;" ::: "memory");
        }
        __syncthreads();

#pragma unroll
        for (int ks = 0; ks < 16; ks += 8) {
            uint32_t af[4][4];
#pragma unroll
            for (int mi = 0; mi < 4; mi++) {
                const float* pa = &shA[s][(m0 + mi * 16 + lr) * PA + ks + lc];
                af[mi][0] = to_tf32_u(pa[0]);
                af[mi][1] = to_tf32_u(pa[8 * PA]);
                af[mi][2] = to_tf32_u(pa[4]);
                af[mi][3] = to_tf32_u(pa[8 * PA + 4]);
            }
            uint32_t bf[4][2];
#pragma unroll
            for (int nj = 0; nj < 4; nj++) {
                if (!TB) {
                    const float* pb = &shB[s][(ks + lc) * PBNN + n0 + nj * 8 + lr];
                    bf[nj][0] = to_tf32_u(pb[0]);
                    bf[nj][1] = to_tf32_u(pb[4 * PBNN]);
                } else {
                    const float* pb = &shB[s][(n0 + nj * 8 + lr) * PA + ks + lc];
                    bf[nj][0] = to_tf32_u(pb[0]);
                    bf[nj][1] = to_tf32_u(pb[4]);
                }
            }
#pragma unroll
            for (int mi = 0; mi < 4; mi++)
#pragma unroll
                for (int nj = 0; nj < 4; nj++) {
                    asm volatile(
                        "mma.sync.aligned.m16n8k8.row.col.f32.tf32.tf32.f32 "
                        "{%0,%1,%2,%3}, {%4,%5,%6,%7}, {%8,%9}, {%0,%1,%2,%3};"
                        : "+f"(acc[mi][nj][0]), "+f"(acc[mi][nj][1]),
                          "+f"(acc[mi][nj][2]), "+f"(acc[mi][nj][3])
                        : "r"(af[mi][0]), "r"(af[mi][1]),
                          "r"(af[mi][2]), "r"(af[mi][3]),
                          "r"(bf[nj][0]), "r"(bf[nj][1]));
                }
        }
        __syncthreads();
    }

    // ---- epilogue ----
#pragma unroll
    for (int mi = 0; mi < 4; mi++) {
        const int r = row0 + m0 + mi * 16 + lr;
        const float bv0 = BIAS ? bias[r]     : 0.f;
        const float bv8 = BIAS ? bias[r + 8] : 0.f;
#pragma unroll
        for (int nj = 0; nj < 4; nj++) {
            const int c = col0 + n0 + nj * 8 + lc * 2;
            float2 v0 = { acc[mi][nj][0] + bv0, acc[mi][nj][1] + bv0 };
            float2 v1 = { acc[mi][nj][2] + bv8, acc[mi][nj][3] + bv8 };
            *(float2*)(C + (size_t)r * ldc + c)       = v0;
            *(float2*)(C + (size_t)(r + 8) * ldc + c) = v1;
        }
    }
}

// ---------------------------------------------------------------------------
// Row softmax over rows of 1024, one 256-thread block per row, in place.
// ---------------------------------------------------------------------------
__global__ __launch_bounds__(256)
void softmax_rows_kernel(float* __restrict__ data)
{
    float* row = data + (size_t)blockIdx.x * NDIM;
    const int tid = threadIdx.x;

    float4 v = *(const float4*)(row + tid * 4);

    float m = fmaxf(fmaxf(v.x, v.y), fmaxf(v.z, v.w));
#pragma unroll
    for (int off = 16; off > 0; off >>= 1)
        m = fmaxf(m, __shfl_xor_sync(0xffffffffu, m, off));
    __shared__ float smax[8];
    __shared__ float ssum[8];
    const int wid = tid >> 5, lid = tid & 31;
    if (lid == 0) smax[wid] = m;
    __syncthreads();
    if (wid == 0) {
        float tt = smax[lid & 7];
#pragma unroll
        for (int off = 4; off > 0; off >>= 1)
            tt = fmaxf(tt, __shfl_xor_sync(0xffffffffu, tt, off));
        if (lid == 0) smax[0] = tt;
    }
    __syncthreads();
    m = smax[0];

    v.x = __expf(v.x - m);
    v.y = __expf(v.y - m);
    v.z = __expf(v.z - m);
    v.w = __expf(v.w - m);
    float s = v.x + v.y + v.z + v.w;
#pragma unroll
    for (int off = 16; off > 0; off >>= 1)
        s += __shfl_xor_sync(0xffffffffu, s, off);
    if (lid == 0) ssum[wid] = s;
    __syncthreads();
    if (wid == 0) {
        float tt = ssum[lid & 7];
#pragma unroll
        for (int off = 4; off > 0; off >>= 1)
            tt += __shfl_xor_sync(0xffffffffu, tt, off);
        if (lid == 0) ssum[0] = tt;
    }
    __syncthreads();
    const float inv = 1.0f / ssum[0];

    v.x *= inv; v.y *= inv; v.z *= inv; v.w *= inv;
    *(float4*)(row + tid * 4) = v;
}

// ---------------------------------------------------------------------------
extern "C" void kernel_launch(void* const* d_in, const int* in_sizes, int n_in,
                              void* d_out, int out_size)
{
    const float* x  = (const float*)d_in[0];
    const float* wA = (const float*)d_in[1];
    const float* bA = (const float*)d_in[2];
    const float* wB = (const float*)d_in[3];
    const float* bB = (const float*)d_in[4];
    const float* wV = (const float*)d_in[5];
    const float* bV = (const float*)d_in[6];
    const float* wR = (const float*)d_in[7];
    const float* bR = (const float*)d_in[8];
    float* out = (float*)d_out;

    float *Am, *Bm, *Vm, *G, *G2;
    cudaGetSymbolAddress((void**)&Am, g_A);
    cudaGetSymbolAddress((void**)&Bm, g_Bm);
    cudaGetSymbolAddress((void**)&Vm, g_Vm);
    cudaGetSymbolAddress((void**)&G,  g_G);
    cudaGetSymbolAddress((void**)&G2, g_G2);

    const size_t sXN = (size_t)CDIM * NDIM;   // 512*1024
    const size_t sCC = (size_t)CDIM * CDIM;   // 512*512

    dim3 blk(256);

    // 1) Projections (NN): A/Bm/Vm = W @ x + b   M=512, N=1024, K=512
    {
        dim3 g(NDIM / 128, CDIM / 128, BSZ);
        mma_gemm_kernel<false, true><<<g, blk>>>(wA, 0, CDIM, x, sXN, NDIM, bA, Am, sXN, NDIM, CDIM);
        mma_gemm_kernel<false, true><<<g, blk>>>(wB, 0, CDIM, x, sXN, NDIM, bB, Bm, sXN, NDIM, CDIM);
        mma_gemm_kernel<false, true><<<g, blk>>>(wV, 0, CDIM, x, sXN, NDIM, bV, Vm, sXN, NDIM, CDIM);
    }

    // 2) softmax over spatial dim
    softmax_rows_kernel<<<BSZ * CDIM, blk>>>(Bm);
    softmax_rows_kernel<<<BSZ * CDIM, blk>>>(Vm);

    // 3) G = A @ Bm^T (NT)   M=512, N=512, K=1024
    {
        dim3 g(CDIM / 128, CDIM / 128, BSZ);
        mma_gemm_kernel<true, false><<<g, blk>>>(Am, sXN, NDIM, Bm, sXN, NDIM, nullptr, G, sCC, CDIM, NDIM);
    }

    // 4) G2 = wR @ G (NN)    M=512, N=512, K=512
    {
        dim3 g(CDIM / 128, CDIM / 128, BSZ);
        mma_gemm_kernel<false, false><<<g, blk>>>(wR, 0, CDIM, G, sCC, CDIM, nullptr, G2, sCC, CDIM, CDIM);
    }

    // 5) out = G2 @ Vm + bR (NN)   M=512, N=1024, K=512
    {
        dim3 g(NDIM / 128, CDIM / 128, BSZ);
        mma_gemm_kernel<false, true><<<g, blk>>>(G2, sCC, CDIM, Vm, sXN, NDIM, bR, out, sXN, NDIM, CDIM);
    }
}

// round 5
// speedup vs baseline: 3.3471x; 1.5514x over previous
#include <cuda_runtime.h>
#include <cstdint>

// ---------------------------------------------------------------------------
// DoubleAttention via mma.sync tf32, R4.
// Key changes vs R3:
//  - All GEMM inputs pre-rounded to tf32 (pre-pass for x/weights; epilogue &
//    softmax round their outputs) -> no cvt in GEMM inner loop (HW truncation
//    of pre-rounded values is exact).
//  - k-permuted fragments: A and NT-B fragment loads vectorized to LDS.128
//    (one float4 feeds both k=8 mmas of a BK=16 chunk). NN-B staged with row
//    permutation rho(k)=((k&3)<<2)|(k>>2) so its scalar loads stay
//    conflict-free.
// ---------------------------------------------------------------------------

#define BSZ   32
#define CDIM  512
#define NDIM  1024

__device__ float g_xr [(size_t)BSZ * CDIM * NDIM];   // rounded x
__device__ float g_w  [4][(size_t)CDIM * CDIM];      // rounded wA,wB,wV,wR
__device__ float g_A  [(size_t)BSZ * CDIM * NDIM];
__device__ float g_Bm [(size_t)BSZ * CDIM * NDIM];
__device__ float g_Vm [(size_t)BSZ * CDIM * NDIM];
__device__ float g_G  [(size_t)BSZ * CDIM * CDIM];
__device__ float g_G2 [(size_t)BSZ * CDIM * CDIM];

__device__ __forceinline__ uint32_t smem_u32(const void* p) {
    uint32_t a;
    asm("{ .reg .u64 t; cvta.to.shared.u64 t, %1; cvt.u32.u64 %0, t; }"
        : "=r"(a) : "l"(p));
    return a;
}
__device__ __forceinline__ void cp16(uint32_t dst, const void* src) {
    asm volatile("cp.async.cg.shared.global [%0], [%1], 16;"
                 :: "r"(dst), "l"(src));
}
__device__ __forceinline__ float rna(float x) {
    float y;
    asm("cvt.rna.tf32.f32 %0, %1;" : "=f"(y) : "f"(x));
    return y;
}

// ---------------------------------------------------------------------------
// Pre-round kernels
// ---------------------------------------------------------------------------
__global__ __launch_bounds__(256)
void preround_kernel(const float4* __restrict__ in, float4* __restrict__ out, int n4)
{
    int i = blockIdx.x * 256 + threadIdx.x;
    if (i < n4) {
        float4 v = in[i];
        v.x = rna(v.x); v.y = rna(v.y); v.z = rna(v.z); v.w = rna(v.w);
        out[i] = v;
    }
}

__global__ __launch_bounds__(256)
void preround_w_kernel(const float4* w0, const float4* w1,
                       const float4* w2, const float4* w3,
                       float4* __restrict__ out)   // out = g_w base (4 contiguous)
{
    const float4* srcs[4] = { w0, w1, w2, w3 };
    const int n4 = CDIM * CDIM / 4;
    const float4* src = srcs[blockIdx.y];
    float4* dst = out + (size_t)blockIdx.y * n4;
    int i = blockIdx.x * 256 + threadIdx.x;
    if (i < n4) {
        float4 v = src[i];
        v.x = rna(v.x); v.y = rna(v.y); v.z = rna(v.z); v.w = rna(v.w);
        dst[i] = v;
    }
}

// ---------------------------------------------------------------------------
// GEMM: C[b][m][n] = sum_k A[b][m][k]*B[b][k][n] (TB=0) / A[m][k]*B[n][k] (TB=1)
// CTA 128x128, 256 thr, 8 warps (2x4 of 64x32 tiles), BK=16, 2-stage cp.async.
// Inputs MUST be tf32-pre-rounded. Output optionally rounded (ROUND).
// ---------------------------------------------------------------------------
#define PBNN 136

template<bool TB, bool BIAS, bool ROUND>
__global__ void __launch_bounds__(256)
mma_gemm_kernel(const float* __restrict__ Ag, size_t sAs, int lda,
                const float* __restrict__ Bg, size_t sBs, int ldb,
                const float* __restrict__ bias,
                float* __restrict__ Cg, size_t sCs, int ldc, int K)
{
    __shared__ float shA[2][128 * 16];      // [m][k], pitch 16, 8KB/stage
    __shared__ float shB[2][16 * PBNN];     // NN: [rho(k)][n] pitch 136 (8.5KB)
                                            // NT: reuses as [n][k] pitch 16 (8KB)
    const int tid  = threadIdx.x;
    const int lane = tid & 31;
    const int wid  = tid >> 5;
    const int m0   = (wid & 1) * 64;
    const int n0   = (wid >> 1) * 32;
    const int row0 = blockIdx.y * 128;
    const int col0 = blockIdx.x * 128;

    const float* A = Ag + (size_t)blockIdx.z * sAs;
    const float* B = Bg + (size_t)blockIdx.z * sBs;
    float*       C = Cg + (size_t)blockIdx.z * sCs;

    const uint32_t saA[2] = { smem_u32(shA[0]), smem_u32(shA[1]) };
    const uint32_t saB[2] = { smem_u32(shB[0]), smem_u32(shB[1]) };

    float acc[4][4][4];
#pragma unroll
    for (int i = 0; i < 4; i++)
#pragma unroll
        for (int j = 0; j < 4; j++)
#pragma unroll
            for (int r = 0; r < 4; r++) acc[i][j][r] = 0.f;

    const int nch = K >> 4;

    auto load_stage = [&](int s, int k0) {
#pragma unroll
        for (int i = 0; i < 2; i++) {              // A: 128 rows x 4 chunks
            const int c  = tid + i * 256;
            const int r  = c >> 2;
            const int cc = c & 3;
            cp16(saA[s] + (uint32_t)(r * 16 + cc * 4) * 4,
                 A + (size_t)(row0 + r) * lda + k0 + cc * 4);
        }
        if (!TB) {
#pragma unroll
            for (int i = 0; i < 2; i++) {          // B NN: 16 k-rows x 32 chunks
                const int c  = tid + i * 256;
                const int j  = c >> 5;             // gmem k-row 0..15
                const int cc = c & 31;
                const int pr = ((j & 3) << 2) | (j >> 2);   // rho(j)
                cp16(saB[s] + (uint32_t)(pr * PBNN + cc * 4) * 4,
                     B + (size_t)(k0 + j) * ldb + col0 + cc * 4);
            }
        } else {
#pragma unroll
            for (int i = 0; i < 2; i++) {          // B NT: 128 n-rows x 4 chunks
                const int c  = tid + i * 256;
                const int r  = c >> 2;
                const int cc = c & 3;
                cp16(saB[s] + (uint32_t)(r * 16 + cc * 4) * 4,
                     B + (size_t)(col0 + r) * ldb + k0 + cc * 4);
            }
        }
        asm volatile("cp.async.commit_group;" ::: "memory");
    };

    load_stage(0, 0);

    const int lr = lane >> 2;   // 0..7
    const int lc = lane & 3;    // 0..3

    for (int ch = 0; ch < nch; ++ch) {
        const int s = ch & 1;
        if (ch + 1 < nch) {
            load_stage(s ^ 1, (ch + 1) << 4);
            asm volatile("cp.async.wait_group 1;" ::: "memory");
        } else {
            asm volatile("cp.async.wait_group 0;" ::: "memory");
        }
        __syncthreads();

        // A fragments: one float4 per (mi, row-half) feeds BOTH k=8 mmas.
        // Logical-k permutation: mma0 col j <-> k=4j(+1 for j>=4),
        //                        mma1 col j <-> k=4j+2(+3).
        float4 a0[4], a8[4];
#pragma unroll
        for (int mi = 0; mi < 4; mi++) {
            a0[mi] = *(const float4*)&shA[s][(m0 + mi * 16 + lr)     * 16 + lc * 4];
            a8[mi] = *(const float4*)&shA[s][(m0 + mi * 16 + lr + 8) * 16 + lc * 4];
        }
        float4 bf[4];
#pragma unroll
        for (int nj = 0; nj < 4; nj++) {
            if (TB) {
                bf[nj] = *(const float4*)&shB[s][(n0 + nj * 8 + lr) * 16 + lc * 4];
            } else {
                const int n = n0 + nj * 8 + lr;
                bf[nj].x = shB[s][(lc)      * PBNN + n];   // rho(4lc)   = lc
                bf[nj].y = shB[s][(4 + lc)  * PBNN + n];   // rho(4lc+1) = 4+lc
                bf[nj].z = shB[s][(8 + lc)  * PBNN + n];   // rho(4lc+2) = 8+lc
                bf[nj].w = shB[s][(12 + lc) * PBNN + n];   // rho(4lc+3) = 12+lc
            }
        }

#pragma unroll
        for (int nj = 0; nj < 4; nj++)
#pragma unroll
            for (int mi = 0; mi < 4; mi++) {
                asm volatile(
                    "mma.sync.aligned.m16n8k8.row.col.f32.tf32.tf32.f32 "
                    "{%0,%1,%2,%3}, {%4,%5,%6,%7}, {%8,%9}, {%0,%1,%2,%3};"
                    : "+f"(acc[mi][nj][0]), "+f"(acc[mi][nj][1]),
                      "+f"(acc[mi][nj][2]), "+f"(acc[mi][nj][3])
                    : "r"(__float_as_uint(a0[mi].x)), "r"(__float_as_uint(a8[mi].x)),
                      "r"(__float_as_uint(a0[mi].y)), "r"(__float_as_uint(a8[mi].y)),
                      "r"(__float_as_uint(bf[nj].x)), "r"(__float_as_uint(bf[nj].y)));
            }
#pragma unroll
        for (int nj = 0; nj < 4; nj++)
#pragma unroll
            for (int mi = 0; mi < 4; mi++) {
                asm volatile(
                    "mma.sync.aligned.m16n8k8.row.col.f32.tf32.tf32.f32 "
                    "{%0,%1,%2,%3}, {%4,%5,%6,%7}, {%8,%9}, {%0,%1,%2,%3};"
                    : "+f"(acc[mi][nj][0]), "+f"(acc[mi][nj][1]),
                      "+f"(acc[mi][nj][2]), "+f"(acc[mi][nj][3])
                    : "r"(__float_as_uint(a0[mi].z)), "r"(__float_as_uint(a8[mi].z)),
                      "r"(__float_as_uint(a0[mi].w)), "r"(__float_as_uint(a8[mi].w)),
                      "r"(__float_as_uint(bf[nj].z)), "r"(__float_as_uint(bf[nj].w)));
            }
        __syncthreads();
    }

    // ---- epilogue ----
#pragma unroll
    for (int mi = 0; mi < 4; mi++) {
        const int r = row0 + m0 + mi * 16 + lr;
        const float bv0 = BIAS ? bias[r]     : 0.f;
        const float bv8 = BIAS ? bias[r + 8] : 0.f;
#pragma unroll
        for (int nj = 0; nj < 4; nj++) {
            const int c = col0 + n0 + nj * 8 + lc * 2;
            float2 v0 = { acc[mi][nj][0] + bv0, acc[mi][nj][1] + bv0 };
            float2 v1 = { acc[mi][nj][2] + bv8, acc[mi][nj][3] + bv8 };
            if (ROUND) {
                v0.x = rna(v0.x); v0.y = rna(v0.y);
                v1.x = rna(v1.x); v1.y = rna(v1.y);
            }
            *(float2*)(C + (size_t)r * ldc + c)       = v0;
            *(float2*)(C + (size_t)(r + 8) * ldc + c) = v1;
        }
    }
}

// ---------------------------------------------------------------------------
// Fused row softmax over rows of 1024 for two arrays (blockIdx.y selects),
// in place, output tf32-rounded.
// ---------------------------------------------------------------------------
__global__ __launch_bounds__(256)
void softmax_rows_kernel(float* __restrict__ d0, float* __restrict__ d1)
{
    float* data = blockIdx.y ? d1 : d0;
    float* row = data + (size_t)blockIdx.x * NDIM;
    const int tid = threadIdx.x;

    float4 v = *(const float4*)(row + tid * 4);

    float m = fmaxf(fmaxf(v.x, v.y), fmaxf(v.z, v.w));
#pragma unroll
    for (int off = 16; off > 0; off >>= 1)
        m = fmaxf(m, __shfl_xor_sync(0xffffffffu, m, off));
    __shared__ float smax[8];
    __shared__ float ssum[8];
    const int wid = tid >> 5, lid = tid & 31;
    if (lid == 0) smax[wid] = m;
    __syncthreads();
    if (wid == 0) {
        float tt = smax[lid & 7];
#pragma unroll
        for (int off = 4; off > 0; off >>= 1)
            tt = fmaxf(tt, __shfl_xor_sync(0xffffffffu, tt, off));
        if (lid == 0) smax[0] = tt;
    }
    __syncthreads();
    m = smax[0];

    v.x = __expf(v.x - m);
    v.y = __expf(v.y - m);
    v.z = __expf(v.z - m);
    v.w = __expf(v.w - m);
    float s = v.x + v.y + v.z + v.w;
#pragma unroll
    for (int off = 16; off > 0; off >>= 1)
        s += __shfl_xor_sync(0xffffffffu, s, off);
    if (lid == 0) ssum[wid] = s;
    __syncthreads();
    if (wid == 0) {
        float tt = ssum[lid & 7];
#pragma unroll
        for (int off = 4; off > 0; off >>= 1)
            tt += __shfl_xor_sync(0xffffffffu, tt, off);
        if (lid == 0) ssum[0] = tt;
    }
    __syncthreads();
    const float inv = 1.0f / ssum[0];

    v.x = rna(v.x * inv); v.y = rna(v.y * inv);
    v.z = rna(v.z * inv); v.w = rna(v.w * inv);
    *(float4*)(row + tid * 4) = v;
}

// ---------------------------------------------------------------------------
extern "C" void kernel_launch(void* const* d_in, const int* in_sizes, int n_in,
                              void* d_out, int out_size)
{
    const float* x  = (const float*)d_in[0];
    const float* wA = (const float*)d_in[1];
    const float* bA = (const float*)d_in[2];
    const float* wB = (const float*)d_in[3];
    const float* bB = (const float*)d_in[4];
    const float* wV = (const float*)d_in[5];
    const float* bV = (const float*)d_in[6];
    const float* wR = (const float*)d_in[7];
    const float* bR = (const float*)d_in[8];
    float* out = (float*)d_out;

    float *xr, *wr, *Am, *Bm, *Vm, *G, *G2;
    cudaGetSymbolAddress((void**)&xr, g_xr);
    cudaGetSymbolAddress((void**)&wr, g_w);
    cudaGetSymbolAddress((void**)&Am, g_A);
    cudaGetSymbolAddress((void**)&Bm, g_Bm);
    cudaGetSymbolAddress((void**)&Vm, g_Vm);
    cudaGetSymbolAddress((void**)&G,  g_G);
    cudaGetSymbolAddress((void**)&G2, g_G2);

    const float* wAr = wr;
    const float* wBr = wr + (size_t)CDIM * CDIM;
    const float* wVr = wr + (size_t)2 * CDIM * CDIM;
    const float* wRr = wr + (size_t)3 * CDIM * CDIM;

    const size_t sXN = (size_t)CDIM * NDIM;
    const size_t sCC = (size_t)CDIM * CDIM;

    dim3 blk(256);

    // 0) pre-round x and weights to tf32
    {
        const int n4x = (int)(BSZ * sXN / 4);
        preround_kernel<<<(n4x + 255) / 256, blk>>>((const float4*)x, (float4*)xr, n4x);
        const int n4w = CDIM * CDIM / 4;
        dim3 gw((n4w + 255) / 256, 4);
        preround_w_kernel<<<gw, blk>>>((const float4*)wA, (const float4*)wB,
                                       (const float4*)wV, (const float4*)wR,
                                       (float4*)wr);
    }

    // 1) Projections (NN): M=512, N=1024, K=512
    {
        dim3 g(NDIM / 128, CDIM / 128, BSZ);
        mma_gemm_kernel<false, true,  true ><<<g, blk>>>(wAr, 0, CDIM, xr, sXN, NDIM, bA, Am, sXN, NDIM, CDIM);
        mma_gemm_kernel<false, true,  false><<<g, blk>>>(wBr, 0, CDIM, xr, sXN, NDIM, bB, Bm, sXN, NDIM, CDIM);
        mma_gemm_kernel<false, true,  false><<<g, blk>>>(wVr, 0, CDIM, xr, sXN, NDIM, bV, Vm, sXN, NDIM, CDIM);
    }

    // 2) softmax over spatial dim (both arrays, rounded output)
    {
        dim3 g(BSZ * CDIM, 2);
        softmax_rows_kernel<<<g, blk>>>(Bm, Vm);
    }

    // 3) G = Am @ Bm^T (NT), M=N=512, K=1024, rounded
    {
        dim3 g(CDIM / 128, CDIM / 128, BSZ);
        mma_gemm_kernel<true, false, true><<<g, blk>>>(Am, sXN, NDIM, Bm, sXN, NDIM, nullptr, G, sCC, CDIM, NDIM);
    }

    // 4) G2 = wR @ G (NN), M=N=K=512, rounded
    {
        dim3 g(CDIM / 128, CDIM / 128, BSZ);
        mma_gemm_kernel<false, false, true><<<g, blk>>>(wRr, 0, CDIM, G, sCC, CDIM, nullptr, G2, sCC, CDIM, CDIM);
    }

    // 5) out = G2 @ Vm + bR (NN), M=512, N=1024, K=512, NOT rounded
    {
        dim3 g(NDIM / 128, CDIM / 128, BSZ);
        mma_gemm_kernel<false, true, false><<<g, blk>>>(G2, sCC, CDIM, Vm, sXN, NDIM, bR, out, sXN, NDIM, CDIM);
    }
}